// round 2
// baseline (speedup 1.0000x reference)
#include <cuda_runtime.h>

#define B_  16
#define C_  256
#define H_  64
#define W_  64
#define K_  31
#define PAD_ 15
#define HW_ 4096
#define TILE_W 94   // 64 + 30 halo
#define TILE_S 95   // padded row stride (odd -> conflict-free scalar LDS across rows)

// Scratch (allocation-free rule: __device__ globals)
__device__ float g_y[(size_t)B_ * C_ * HW_];     // dwconv output, 256 MB
__device__ float g_psum[C_ * B_];
__device__ float g_psumsq[C_ * B_];
__device__ float g_scale[C_];
__device__ float g_bias[C_];

// Packed f32x2 helpers (Blackwell sm_103a; FFMA2 only reachable via PTX)
#define PACK2(d, lo, hi) \
    asm("mov.b64 %0, {%1, %2};" : "=l"(d) : "r"(__float_as_uint(lo)), "r"(__float_as_uint(hi)))
#define FMA2(d, a, b) \
    asm("fma.rn.f32x2 %0, %1, %2, %0;" : "+l"(d) : "l"(a), "l"(b))
#define UNPACK2(lo, hi, v) \
    asm("mov.b64 {%0, %1}, %2;" : "=r"(lo), "=r"(hi) : "l"(v))

// ---------------------------------------------------------------------------
// Kernel 1: depthwise 31x31 conv with packed FFMA2, one (b,c) image per block,
// fused per-block sum / sumsq partials.
// ---------------------------------------------------------------------------
__global__ __launch_bounds__(256) void dwconv_kernel(const float* __restrict__ x,
                                                     const float* __restrict__ dw) {
    __shared__ float  tile[TILE_W * TILE_S];
    __shared__ float2 wsm2[K_ * K_];          // duplicated weights: (w,w) pairs
    __shared__ float  red[2][8];

    const int bx  = blockIdx.x;
    const int c   = bx & (C_ - 1);
    const int b   = bx >> 8;
    const int tid = threadIdx.x;

    // weights for this channel, duplicated for packed broadcast via LDS.64
    const float* wp = dw + c * (K_ * K_);
    for (int i = tid; i < K_ * K_; i += 256) {
        float w = wp[i];
        wsm2[i] = make_float2(w, w);
    }

    // input tile with zero-padded halo
    const float* xp = x + (size_t)(b * C_ + c) * HW_;
    for (int i = tid; i < TILE_W * TILE_W; i += 256) {
        int tr = i / TILE_W;
        int tc = i - tr * TILE_W;
        int gh = tr - PAD_;
        int gw = tc - PAD_;
        float v = 0.0f;
        if ((unsigned)gh < (unsigned)H_ && (unsigned)gw < (unsigned)W_)
            v = xp[gh * W_ + gw];
        tile[tr * TILE_S + tc] = v;
    }
    __syncthreads();

    // thread -> (row h, col block w0): warp spans 32 consecutive rows, same w0
    const int h  = tid & 63;
    const int w0 = (tid >> 6) << 4;   // 0,16,32,48

    unsigned long long acc2[8];       // 8 packed pairs = 16 outputs
    #pragma unroll
    for (int i = 0; i < 8; ++i) acc2[i] = 0ULL;

    #pragma unroll 1
    for (int kh = 0; kh < K_; ++kh) {
        const float* xr = &tile[(h + kh) * TILE_S + w0];

        // scalar window loads (conflict-free), then pack two phase views
        float win[46];
        #pragma unroll
        for (int t = 0; t < 46; ++t) win[t] = xr[t];

        unsigned long long pe[23];    // (win[2t],   win[2t+1])
        unsigned long long po[22];    // (win[2t+1], win[2t+2])
        #pragma unroll
        for (int t = 0; t < 23; ++t) PACK2(pe[t], win[2 * t], win[2 * t + 1]);
        #pragma unroll
        for (int t = 0; t < 22; ++t) PACK2(po[t], win[2 * t + 1], win[2 * t + 2]);

        const unsigned long long* wrow =
            reinterpret_cast<const unsigned long long*>(&wsm2[kh * K_]);

        #pragma unroll
        for (int kw = 0; kw < K_; ++kw) {
            const unsigned long long wpair = wrow[kw];   // LDS.64 broadcast
            const unsigned long long* src = (kw & 1) ? &po[kw >> 1] : &pe[kw >> 1];
            #pragma unroll
            for (int i = 0; i < 8; ++i)
                FMA2(acc2[i], src[i], wpair);
        }
    }

    // unpack, store y, accumulate statistics
    float* yp = g_y + (size_t)(b * C_ + c) * HW_ + h * W_ + w0;
    float s = 0.0f, s2 = 0.0f;
    #pragma unroll
    for (int i = 0; i < 8; ++i) {
        unsigned int lo, hi;
        UNPACK2(lo, hi, acc2[i]);
        float v0 = __uint_as_float(lo);
        float v1 = __uint_as_float(hi);
        yp[2 * i]     = v0;
        yp[2 * i + 1] = v1;
        s  += v0 + v1;
        s2  = fmaf(v0, v0, s2);
        s2  = fmaf(v1, v1, s2);
    }
    #pragma unroll
    for (int off = 16; off > 0; off >>= 1) {
        s  += __shfl_down_sync(0xffffffffu, s,  off);
        s2 += __shfl_down_sync(0xffffffffu, s2, off);
    }
    const int warp = tid >> 5;
    const int lane = tid & 31;
    if (lane == 0) { red[0][warp] = s; red[1][warp] = s2; }
    __syncthreads();
    if (tid == 0) {
        float ts = 0.0f, t2 = 0.0f;
        #pragma unroll
        for (int w = 0; w < 8; ++w) { ts += red[0][w]; t2 += red[1][w]; }
        g_psum[c * B_ + b]   = ts;
        g_psumsq[c * B_ + b] = t2;
    }
}

// ---------------------------------------------------------------------------
// Kernel 2: fold B partials per channel -> scale/bias  (deterministic)
// ---------------------------------------------------------------------------
__global__ void stats_kernel(const float* __restrict__ gamma,
                             const float* __restrict__ beta) {
    const int c = threadIdx.x;
    float s = 0.0f, s2 = 0.0f;
    #pragma unroll
    for (int b = 0; b < B_; ++b) {
        s  += g_psum[c * B_ + b];
        s2 += g_psumsq[c * B_ + b];
    }
    const float inv  = 1.0f / (float)(B_ * HW_);
    const float mean = s * inv;
    const float var  = s2 * inv - mean * mean;
    const float rstd = rsqrtf(var + 1e-5f);
    const float sc   = rstd * gamma[c];
    g_scale[c] = sc;
    g_bias[c]  = beta[c] - mean * sc;
}

// ---------------------------------------------------------------------------
// Kernel 3: fused normalize+ReLU+pointwise GEMM
// out[b,o,hw] = sum_c pw[o,c] * relu(y[b,c,hw]*scale[c] + bias[c])
// Tile: 64 (o) x 64 (pixels), K-step 16, 4x4 micro-tile per thread.
// ---------------------------------------------------------------------------
__global__ __launch_bounds__(256) void pw_kernel(const float* __restrict__ pw,
                                                 float* __restrict__ out) {
    __shared__ float As[16][64];   // As[k][m] = pw[m0+m, c0+k]
    __shared__ float Bs[16][64];   // Bs[k][n] = relu(y*scale+bias)

    const int b   = blockIdx.z;
    const int m0  = blockIdx.y * 64;
    const int hw0 = blockIdx.x * 64;
    const int tid = threadIdx.x;
    const int tm  = tid >> 4;      // 0..15
    const int tn  = tid & 15;      // 0..15

    // loader indices
    const int la_m  = tid >> 2;        // 0..63
    const int la_k4 = (tid & 3) * 4;   // 0,4,8,12
    const int lb_k  = tid >> 4;        // 0..15
    const int lb_n  = (tid & 15) * 4;  // 0..60

    const float* yb = g_y + (size_t)b * C_ * HW_ + hw0;

    float acc[4][4];
    #pragma unroll
    for (int i = 0; i < 4; ++i)
        #pragma unroll
        for (int j = 0; j < 4; ++j) acc[i][j] = 0.0f;

    for (int c0 = 0; c0 < C_; c0 += 16) {
        // A tile
        float4 a4 = *(const float4*)&pw[(m0 + la_m) * C_ + c0 + la_k4];
        As[la_k4 + 0][la_m] = a4.x;
        As[la_k4 + 1][la_m] = a4.y;
        As[la_k4 + 2][la_m] = a4.z;
        As[la_k4 + 3][la_m] = a4.w;
        // B tile with fused normalize + relu
        {
            const int cc = c0 + lb_k;
            float4 b4 = *(const float4*)&yb[(size_t)cc * HW_ + lb_n];
            const float sc = g_scale[cc];
            const float bi = g_bias[cc];
            b4.x = fmaxf(fmaf(b4.x, sc, bi), 0.0f);
            b4.y = fmaxf(fmaf(b4.y, sc, bi), 0.0f);
            b4.z = fmaxf(fmaf(b4.z, sc, bi), 0.0f);
            b4.w = fmaxf(fmaf(b4.w, sc, bi), 0.0f);
            *(float4*)&Bs[lb_k][lb_n] = b4;
        }
        __syncthreads();

        #pragma unroll
        for (int kk = 0; kk < 16; ++kk) {
            const float4 av = *(const float4*)&As[kk][tm * 4];
            const float4 bv = *(const float4*)&Bs[kk][tn * 4];
            const float a_[4] = {av.x, av.y, av.z, av.w};
            const float b_[4] = {bv.x, bv.y, bv.z, bv.w};
            #pragma unroll
            for (int i = 0; i < 4; ++i)
                #pragma unroll
                for (int j = 0; j < 4; ++j)
                    acc[i][j] = fmaf(a_[i], b_[j], acc[i][j]);
        }
        __syncthreads();
    }

    // write 4x4 micro-tile
    #pragma unroll
    for (int i = 0; i < 4; ++i) {
        const int o = m0 + tm * 4 + i;
        float4 ov;
        ov.x = acc[i][0]; ov.y = acc[i][1]; ov.z = acc[i][2]; ov.w = acc[i][3];
        *(float4*)&out[(size_t)(b * C_ + o) * HW_ + hw0 + tn * 4] = ov;
    }
}

// ---------------------------------------------------------------------------
extern "C" void kernel_launch(void* const* d_in, const int* in_sizes, int n_in,
                              void* d_out, int out_size) {
    const float* x     = (const float*)d_in[0];  // (16,256,64,64)
    const float* dw    = (const float*)d_in[1];  // (256,1,31,31)
    const float* gamma = (const float*)d_in[2];  // (256,)
    const float* beta  = (const float*)d_in[3];  // (256,)
    const float* pw    = (const float*)d_in[4];  // (256,256)
    float* out = (float*)d_out;                  // (16,256,64,64)

    dwconv_kernel<<<B_ * C_, 256>>>(x, dw);
    stats_kernel<<<1, C_>>>(gamma, beta);
    pw_kernel<<<dim3(HW_ / 64, C_ / 64, B_), 256>>>(pw, out);
}

// round 3
// speedup vs baseline: 1.1105x; 1.1105x over previous
#include <cuda_runtime.h>

#define B_  16
#define C_  256
#define H_  64
#define W_  64
#define K_  31
#define PAD_ 15
#define HW_ 4096
#define TILE_W 94        // 64 + 30 halo
#define SE_   49         // float2 row stride for pe/po: 49 % 16 == 1 -> conflict-free LDS.64
#define PE_T  47         // even-phase pairs per row
#define PO_T  46         // odd-phase pairs per row
#define WROW  32         // padded weight row (float2 per kh)

// dwconv dynamic smem layout (in float2 units)
#define OFF_PE 0
#define OFF_PO (TILE_W * SE_)
#define OFF_W  (2 * TILE_W * SE_)
#define SMEM_F2 (2 * TILE_W * SE_ + K_ * WROW)
#define DW_SMEM_BYTES (SMEM_F2 * 8)

// Scratch (allocation-free rule: __device__ globals)
__device__ float g_y[(size_t)B_ * C_ * HW_];     // dwconv output, 256 MB
__device__ float g_psum[C_ * B_];
__device__ float g_psumsq[C_ * B_];
__device__ float g_scale[C_];
__device__ float g_bias[C_];

// Packed f32x2 FMA (Blackwell sm_103a; only reachable via PTX)
#define FMA2(d, a, b) \
    asm("fma.rn.f32x2 %0, %1, %2, %0;" : "+l"(d) : "l"(a), "l"(b))

union U2F { unsigned long long u; float2 f; };

// ---------------------------------------------------------------------------
// Kernel 1: depthwise 31x31 conv. Hot loop = pure LDS.64 + FFMA2 (no packs).
// ---------------------------------------------------------------------------
__global__ __launch_bounds__(256) void dwconv_kernel(const float* __restrict__ x,
                                                     const float* __restrict__ dw) {
    extern __shared__ float2 sm[];
    float2* pe   = sm + OFF_PE;     // pe[r][t] = (tile(r,2t),   tile(r,2t+1))
    float2* po   = sm + OFF_PO;     // po[r][t] = (tile(r,2t+1), tile(r,2t+2))
    float2* wsm2 = sm + OFF_W;      // duplicated weights, padded rows of 32
    __shared__ float red[2][8];

    const int bx  = blockIdx.x;
    const int c   = bx & (C_ - 1);
    const int b   = bx >> 8;
    const int tid = threadIdx.x;

    // weights for this channel, duplicated (w,w)
    const float* wp = dw + c * (K_ * K_);
    for (int i = tid; i < K_ * K_; i += 256) {
        int kh = i / K_, kw = i - kh * K_;
        float w = wp[i];
        wsm2[kh * WROW + kw] = make_float2(w, w);
    }

    // build even-phase pairs straight from gmem (zero-padded halo)
    const float* xp = x + (size_t)(b * C_ + c) * HW_;
    for (int i = tid; i < TILE_W * PE_T; i += 256) {
        int tr = i / PE_T;
        int t  = i - tr * PE_T;
        int gh = tr - PAD_;
        int g0 = 2 * t - PAD_;
        float v0 = 0.0f, v1 = 0.0f;
        if ((unsigned)gh < (unsigned)H_) {
            const float* xr = xp + gh * W_;
            if ((unsigned)g0       < (unsigned)W_) v0 = xr[g0];
            if ((unsigned)(g0 + 1) < (unsigned)W_) v1 = xr[g0 + 1];
        }
        pe[tr * SE_ + t] = make_float2(v0, v1);
    }
    __syncthreads();

    // odd-phase pairs from pe (SMEM-only)
    for (int i = tid; i < TILE_W * PO_T; i += 256) {
        int tr = i / PO_T;
        int t  = i - tr * PO_T;
        float2 a = pe[tr * SE_ + t];
        float2 bb = pe[tr * SE_ + t + 1];
        po[tr * SE_ + t] = make_float2(a.y, bb.x);
    }
    __syncthreads();

    // thread -> (row h, col block w0): warp spans 32 consecutive rows, same w0
    const int h  = tid & 63;
    const int w0 = (tid >> 6) << 4;   // 0,16,32,48

    unsigned long long acc2[8];       // 8 packed pairs = 16 outputs
    #pragma unroll
    for (int i = 0; i < 8; ++i) acc2[i] = 0ULL;

    const unsigned long long* eR = (const unsigned long long*)(pe + h * SE_ + (w0 >> 1));
    const unsigned long long* oR = (const unsigned long long*)(po + h * SE_ + (w0 >> 1));
    const unsigned long long* wR = (const unsigned long long*)wsm2;

    #pragma unroll 1
    for (int kh = 0; kh < K_; ++kh) {
        unsigned long long e[23], o[22];
        #pragma unroll
        for (int t = 0; t < 8; ++t) { e[t] = eR[t]; o[t] = oR[t]; }
        #pragma unroll
        for (int kwp = 0; kwp < 15; ++kwp) {
            e[kwp + 8] = eR[kwp + 8];
            if (kwp < 14) o[kwp + 8] = oR[kwp + 8];
            const unsigned long long we = wR[2 * kwp];
            const unsigned long long wo = wR[2 * kwp + 1];
            #pragma unroll
            for (int i = 0; i < 8; ++i) FMA2(acc2[i], e[kwp + i], we);
            #pragma unroll
            for (int i = 0; i < 8; ++i) FMA2(acc2[i], o[kwp + i], wo);
        }
        {
            const unsigned long long we = wR[30];
            #pragma unroll
            for (int i = 0; i < 8; ++i) FMA2(acc2[i], e[15 + i], we);
        }
        eR += SE_;
        oR += SE_;
        wR += WROW;
    }

    // store y (float2) + statistics
    float* yp = g_y + (size_t)(b * C_ + c) * HW_ + h * W_ + w0;
    float s = 0.0f, s2 = 0.0f;
    #pragma unroll
    for (int i = 0; i < 8; ++i) {
        U2F u; u.u = acc2[i];
        *(float2*)(yp + 2 * i) = u.f;
        s  += u.f.x + u.f.y;
        s2  = fmaf(u.f.x, u.f.x, s2);
        s2  = fmaf(u.f.y, u.f.y, s2);
    }
    #pragma unroll
    for (int off = 16; off > 0; off >>= 1) {
        s  += __shfl_down_sync(0xffffffffu, s,  off);
        s2 += __shfl_down_sync(0xffffffffu, s2, off);
    }
    const int warp = tid >> 5;
    const int lane = tid & 31;
    if (lane == 0) { red[0][warp] = s; red[1][warp] = s2; }
    __syncthreads();
    if (tid == 0) {
        float ts = 0.0f, t2 = 0.0f;
        #pragma unroll
        for (int w = 0; w < 8; ++w) { ts += red[0][w]; t2 += red[1][w]; }
        g_psum[c * B_ + b]   = ts;
        g_psumsq[c * B_ + b] = t2;
    }
}

// ---------------------------------------------------------------------------
// Kernel 2: fold B partials per channel -> scale/bias  (deterministic)
// ---------------------------------------------------------------------------
__global__ void stats_kernel(const float* __restrict__ gamma,
                             const float* __restrict__ beta) {
    const int c = threadIdx.x;
    float s = 0.0f, s2 = 0.0f;
    #pragma unroll
    for (int b = 0; b < B_; ++b) {
        s  += g_psum[c * B_ + b];
        s2 += g_psumsq[c * B_ + b];
    }
    const float inv  = 1.0f / (float)(B_ * HW_);
    const float mean = s * inv;
    const float var  = s2 * inv - mean * mean;
    const float rstd = rsqrtf(var + 1e-5f);
    const float sc   = rstd * gamma[c];
    g_scale[c] = sc;
    g_bias[c]  = beta[c] - mean * sc;
}

// ---------------------------------------------------------------------------
// Kernel 3: fused normalize+ReLU+pointwise GEMM with FFMA2 + reg double-buffer
// out[b,o,hw] = sum_c pw[o,c] * relu(y[b,c,hw]*scale[c] + bias[c])
// ---------------------------------------------------------------------------
__global__ __launch_bounds__(256) void pw_kernel(const float* __restrict__ pw,
                                                 float* __restrict__ out) {
    __shared__ float2 As2[16][64];  // As2[k][m] = (pw[m0+m,c0+k], same)  duplicated
    __shared__ float  Bs[16][64];   // Bs[k][n]  = relu(y*scale+bias)

    const int b   = blockIdx.z;
    const int m0  = blockIdx.y * 64;
    const int hw0 = blockIdx.x * 64;
    const int tid = threadIdx.x;
    const int tm  = tid >> 4;      // 0..15
    const int tn  = tid & 15;      // 0..15

    const int la_m  = tid >> 2;        // 0..63
    const int la_k4 = (tid & 3) * 4;   // 0,4,8,12
    const int lb_k  = tid >> 4;        // 0..15
    const int lb_n  = (tid & 15) * 4;  // 0..60

    const float* yb = g_y + (size_t)b * C_ * HW_ + hw0;

    unsigned long long acc2[4][2];
    #pragma unroll
    for (int i = 0; i < 4; ++i) { acc2[i][0] = 0ULL; acc2[i][1] = 0ULL; }

    // prefetch first tiles
    float4 a4 = *(const float4*)&pw[(m0 + la_m) * C_ + la_k4];
    float4 b4 = *(const float4*)&yb[(size_t)lb_k * HW_ + lb_n];

    for (int c0 = 0; c0 < C_; c0 += 16) {
        // commit current regs to smem (fused norm+relu on B)
        As2[la_k4 + 0][la_m] = make_float2(a4.x, a4.x);
        As2[la_k4 + 1][la_m] = make_float2(a4.y, a4.y);
        As2[la_k4 + 2][la_m] = make_float2(a4.z, a4.z);
        As2[la_k4 + 3][la_m] = make_float2(a4.w, a4.w);
        {
            const int cc = c0 + lb_k;
            const float sc = g_scale[cc];
            const float bi = g_bias[cc];
            float4 r;
            r.x = fmaxf(fmaf(b4.x, sc, bi), 0.0f);
            r.y = fmaxf(fmaf(b4.y, sc, bi), 0.0f);
            r.z = fmaxf(fmaf(b4.z, sc, bi), 0.0f);
            r.w = fmaxf(fmaf(b4.w, sc, bi), 0.0f);
            *(float4*)&Bs[lb_k][lb_n] = r;
        }
        __syncthreads();

        // prefetch next tiles (hidden behind compute)
        if (c0 + 16 < C_) {
            a4 = *(const float4*)&pw[(m0 + la_m) * C_ + c0 + 16 + la_k4];
            b4 = *(const float4*)&yb[(size_t)(c0 + 16 + lb_k) * HW_ + lb_n];
        }

        #pragma unroll
        for (int kk = 0; kk < 16; ++kk) {
            float4 bv = *(const float4*)&Bs[kk][tn * 4];
            U2F b0, b1;
            b0.f = make_float2(bv.x, bv.y);
            b1.f = make_float2(bv.z, bv.w);
            #pragma unroll
            for (int i = 0; i < 4; ++i) {
                unsigned long long av =
                    *(const unsigned long long*)&As2[kk][tm * 4 + i];
                FMA2(acc2[i][0], b0.u, av);
                FMA2(acc2[i][1], b1.u, av);
            }
        }
        __syncthreads();
    }

    // write 4x4 micro-tile
    #pragma unroll
    for (int i = 0; i < 4; ++i) {
        const int o = m0 + tm * 4 + i;
        U2F lo, hi;
        lo.u = acc2[i][0];
        hi.u = acc2[i][1];
        float4 ov;
        ov.x = lo.f.x; ov.y = lo.f.y; ov.z = hi.f.x; ov.w = hi.f.y;
        *(float4*)&out[(size_t)(b * C_ + o) * HW_ + hw0 + tn * 4] = ov;
    }
}

// ---------------------------------------------------------------------------
extern "C" void kernel_launch(void* const* d_in, const int* in_sizes, int n_in,
                              void* d_out, int out_size) {
    const float* x     = (const float*)d_in[0];  // (16,256,64,64)
    const float* dw    = (const float*)d_in[1];  // (256,1,31,31)
    const float* gamma = (const float*)d_in[2];  // (256,)
    const float* beta  = (const float*)d_in[3];  // (256,)
    const float* pw    = (const float*)d_in[4];  // (256,256)
    float* out = (float*)d_out;                  // (16,256,64,64)

    cudaFuncSetAttribute(dwconv_kernel,
                         cudaFuncAttributeMaxDynamicSharedMemorySize,
                         DW_SMEM_BYTES);

    dwconv_kernel<<<B_ * C_, 256, DW_SMEM_BYTES>>>(x, dw);
    stats_kernel<<<1, C_>>>(gamma, beta);
    pw_kernel<<<dim3(HW_ / 64, C_ / 64, B_), 256>>>(pw, out);
}

// round 4
// speedup vs baseline: 1.3818x; 1.2444x over previous
#include <cuda_runtime.h>

#define B_  16
#define C_  256
#define H_  64
#define W_  64
#define K_  31
#define PAD_ 15
#define HW_ 4096

// dwconv: vertical-pair packed tile
#define PV_ROWS 62          // r = 0..61 ; pair (tile r, tile r+32)
#define PV_COLS 94          // 64 + 30 halo
#define PV_S    95          // f2 row stride (odd -> conflict-free LDS.64 across rows)
#define WROW    32          // padded weight row (f2 per kh)
#define DW_SMEM_BYTES ((PV_ROWS * PV_S + K_ * WROW) * 8)

// Scratch (allocation-free rule: __device__ globals)
__device__ float g_y[(size_t)B_ * C_ * HW_];
__device__ float g_psum[C_ * B_];
__device__ float g_psumsq[C_ * B_];
__device__ float g_scale[C_];
__device__ float g_bias[C_];

// Packed f32x2 FMA (Blackwell sm_103a; only reachable via PTX)
#define FMA2(d, a, b) \
    asm("fma.rn.f32x2 %0, %1, %2, %0;" : "+l"(d) : "l"(a), "l"(b))

union U2F { unsigned long long u; float2 f; };

// ---------------------------------------------------------------------------
// Kernel 1: depthwise 31x31 conv, vertical-pair FFMA2.
// 128 threads: lane = output row h (0..31, also h+32), tid>>5 = col group.
// Hot loop: pure LDS.64 + FFMA2, no packing movs, no phase duplication.
// ---------------------------------------------------------------------------
__global__ void __launch_bounds__(128, 3)
dwconv_kernel(const float* __restrict__ x, const float* __restrict__ dw) {
    extern __shared__ float2 sm[];
    float2* pv   = sm;                       // pv[r*95+c] = (tile(r,c), tile(r+32,c))
    float2* wsm2 = sm + PV_ROWS * PV_S;      // duplicated weights (w,w), rows padded to 32
    __shared__ float red[2][4];

    const int bx  = blockIdx.x;
    const int c   = bx & (C_ - 1);
    const int b   = bx >> 8;
    const int tid = threadIdx.x;

    // weights for this channel, duplicated (w,w)
    const float* wp = dw + c * (K_ * K_);
    for (int i = tid; i < K_ * K_; i += 128) {
        int kh = i / K_, kw = i - kh * K_;
        float w = wp[i];
        wsm2[kh * WROW + kw] = make_float2(w, w);
    }

    // build vertical-pair tile straight from gmem (zero-padded halo)
    const float* xp = x + (size_t)(b * C_ + c) * HW_;
    for (int i = tid; i < PV_ROWS * PV_COLS; i += 128) {
        int r  = i / PV_COLS;
        int cc = i - r * PV_COLS;
        int gw = cc - PAD_;
        float v0 = 0.0f, v1 = 0.0f;
        if ((unsigned)gw < (unsigned)W_) {
            int gh0 = r - PAD_;           // tile row r
            int gh1 = r + 32 - PAD_;      // tile row r+32
            if ((unsigned)gh0 < (unsigned)H_) v0 = xp[gh0 * W_ + gw];
            if ((unsigned)gh1 < (unsigned)H_) v1 = xp[gh1 * W_ + gw];
        }
        pv[r * PV_S + cc] = make_float2(v0, v1);
    }
    __syncthreads();

    const int h  = tid & 31;          // output rows h and h+32
    const int w0 = (tid >> 5) << 4;   // 0,16,32,48

    unsigned long long acc2[16];      // acc2[j] = (out[h][w0+j], out[h+32][w0+j])
    #pragma unroll
    for (int j = 0; j < 16; ++j) acc2[j] = 0ULL;

    const unsigned long long* pvR =
        (const unsigned long long*)pv + (size_t)h * PV_S + w0;
    const unsigned long long* wR = (const unsigned long long*)wsm2;

    #pragma unroll 1
    for (int kh = 0; kh < K_; ++kh) {
        unsigned long long win[46];
        #pragma unroll
        for (int t = 0; t < 46; ++t) win[t] = pvR[t];
        #pragma unroll
        for (int kw = 0; kw < K_; ++kw) {
            const unsigned long long wpair = wR[kw];    // broadcast LDS.64
            #pragma unroll
            for (int j = 0; j < 16; ++j)
                FMA2(acc2[j], win[j + kw], wpair);
        }
        pvR += PV_S;
        wR  += WROW;
    }

    // unpack into two rows, store y, accumulate statistics
    float* ypA = g_y + (size_t)(b * C_ + c) * HW_ + h * W_ + w0;
    float* ypB = ypA + 32 * W_;
    float s = 0.0f, s2 = 0.0f;
    float rowA[16], rowB[16];
    #pragma unroll
    for (int j = 0; j < 16; ++j) {
        U2F u; u.u = acc2[j];
        rowA[j] = u.f.x;
        rowB[j] = u.f.y;
        s  += u.f.x + u.f.y;
        s2  = fmaf(u.f.x, u.f.x, s2);
        s2  = fmaf(u.f.y, u.f.y, s2);
    }
    #pragma unroll
    for (int q = 0; q < 4; ++q) {
        *(float4*)(ypA + 4 * q) = make_float4(rowA[4*q], rowA[4*q+1], rowA[4*q+2], rowA[4*q+3]);
        *(float4*)(ypB + 4 * q) = make_float4(rowB[4*q], rowB[4*q+1], rowB[4*q+2], rowB[4*q+3]);
    }
    #pragma unroll
    for (int off = 16; off > 0; off >>= 1) {
        s  += __shfl_down_sync(0xffffffffu, s,  off);
        s2 += __shfl_down_sync(0xffffffffu, s2, off);
    }
    const int warp = tid >> 5;
    const int lane = tid & 31;
    if (lane == 0) { red[0][warp] = s; red[1][warp] = s2; }
    __syncthreads();
    if (tid == 0) {
        float ts = 0.0f, t2 = 0.0f;
        #pragma unroll
        for (int w = 0; w < 4; ++w) { ts += red[0][w]; t2 += red[1][w]; }
        g_psum[c * B_ + b]   = ts;
        g_psumsq[c * B_ + b] = t2;
    }
}

// ---------------------------------------------------------------------------
// Kernel 2: fold B partials per channel -> scale/bias  (deterministic)
// ---------------------------------------------------------------------------
__global__ void stats_kernel(const float* __restrict__ gamma,
                             const float* __restrict__ beta) {
    const int c = threadIdx.x;
    float s = 0.0f, s2 = 0.0f;
    #pragma unroll
    for (int b = 0; b < B_; ++b) {
        s  += g_psum[c * B_ + b];
        s2 += g_psumsq[c * B_ + b];
    }
    const float inv  = 1.0f / (float)(B_ * HW_);
    const float mean = s * inv;
    const float var  = s2 * inv - mean * mean;
    const float rstd = rsqrtf(var + 1e-5f);
    const float sc   = rstd * gamma[c];
    g_scale[c] = sc;
    g_bias[c]  = beta[c] - mean * sc;
}

// ---------------------------------------------------------------------------
// Kernel 3: fused normalize+ReLU+pointwise GEMM (round-1 proven version)
// ---------------------------------------------------------------------------
__global__ __launch_bounds__(256) void pw_kernel(const float* __restrict__ pw,
                                                 float* __restrict__ out) {
    __shared__ float As[16][64];   // As[k][m] = pw[m0+m, c0+k]
    __shared__ float Bs[16][64];   // Bs[k][n] = relu(y*scale+bias)

    const int b   = blockIdx.z;
    const int m0  = blockIdx.y * 64;
    const int hw0 = blockIdx.x * 64;
    const int tid = threadIdx.x;
    const int tm  = tid >> 4;
    const int tn  = tid & 15;

    const int la_m  = tid >> 2;
    const int la_k4 = (tid & 3) * 4;
    const int lb_k  = tid >> 4;
    const int lb_n  = (tid & 15) * 4;

    const float* yb = g_y + (size_t)b * C_ * HW_ + hw0;

    float acc[4][4];
    #pragma unroll
    for (int i = 0; i < 4; ++i)
        #pragma unroll
        for (int j = 0; j < 4; ++j) acc[i][j] = 0.0f;

    for (int c0 = 0; c0 < C_; c0 += 16) {
        float4 a4 = *(const float4*)&pw[(m0 + la_m) * C_ + c0 + la_k4];
        As[la_k4 + 0][la_m] = a4.x;
        As[la_k4 + 1][la_m] = a4.y;
        As[la_k4 + 2][la_m] = a4.z;
        As[la_k4 + 3][la_m] = a4.w;
        {
            const int cc = c0 + lb_k;
            float4 b4 = *(const float4*)&yb[(size_t)cc * HW_ + lb_n];
            const float sc = g_scale[cc];
            const float bi = g_bias[cc];
            b4.x = fmaxf(fmaf(b4.x, sc, bi), 0.0f);
            b4.y = fmaxf(fmaf(b4.y, sc, bi), 0.0f);
            b4.z = fmaxf(fmaf(b4.z, sc, bi), 0.0f);
            b4.w = fmaxf(fmaf(b4.w, sc, bi), 0.0f);
            *(float4*)&Bs[lb_k][lb_n] = b4;
        }
        __syncthreads();

        #pragma unroll
        for (int kk = 0; kk < 16; ++kk) {
            const float4 av = *(const float4*)&As[kk][tm * 4];
            const float4 bv = *(const float4*)&Bs[kk][tn * 4];
            const float a_[4] = {av.x, av.y, av.z, av.w};
            const float b_[4] = {bv.x, bv.y, bv.z, bv.w};
            #pragma unroll
            for (int i = 0; i < 4; ++i)
                #pragma unroll
                for (int j = 0; j < 4; ++j)
                    acc[i][j] = fmaf(a_[i], b_[j], acc[i][j]);
        }
        __syncthreads();
    }

    #pragma unroll
    for (int i = 0; i < 4; ++i) {
        const int o = m0 + tm * 4 + i;
        float4 ov;
        ov.x = acc[i][0]; ov.y = acc[i][1]; ov.z = acc[i][2]; ov.w = acc[i][3];
        *(float4*)&out[(size_t)(b * C_ + o) * HW_ + hw0 + tn * 4] = ov;
    }
}

// ---------------------------------------------------------------------------
extern "C" void kernel_launch(void* const* d_in, const int* in_sizes, int n_in,
                              void* d_out, int out_size) {
    const float* x     = (const float*)d_in[0];  // (16,256,64,64)
    const float* dw    = (const float*)d_in[1];  // (256,1,31,31)
    const float* gamma = (const float*)d_in[2];  // (256,)
    const float* beta  = (const float*)d_in[3];  // (256,)
    const float* pw    = (const float*)d_in[4];  // (256,256)
    float* out = (float*)d_out;                  // (16,256,64,64)

    cudaFuncSetAttribute(dwconv_kernel,
                         cudaFuncAttributeMaxDynamicSharedMemorySize,
                         DW_SMEM_BYTES);

    dwconv_kernel<<<B_ * C_, 128, DW_SMEM_BYTES>>>(x, dw);
    stats_kernel<<<1, C_>>>(gamma, beta);
    pw_kernel<<<dim3(HW_ / 64, C_ / 64, B_), 256>>>(pw, out);
}